// round 2
// baseline (speedup 1.0000x reference)
#include <cuda_runtime.h>

#define NIMG  4
#define KCH   21
#define NPIX  4096      // 64*64
#define TILE  128
#define NT    32        // NPIX / TILE
#define NPAIR 528       // NT*(NT+1)/2
#define HW    16384     // 128*128

typedef unsigned long long u64;

// Scratch (device globals; no allocation in kernel_launch)
__device__ float g_sroi[NIMG][KCH][NPIX];   // seg (2x2 avg) * roi
__device__ float g_feat[NIMG][5][NPIX];     // x/50, y/50, r/15, g/15, b/15
__device__ float g_sq  [NIMG][NPIX];        // |f|^2
__device__ float g_gate[NIMG][NPIX];
__device__ float g_partial[NIMG * NPAIR];
__device__ int   g_ctr;                     // zero-init; reset by last block

// ---- packed f32x2 helpers (sm_103a dual-pumped FP32) ----
__device__ __forceinline__ u64 pk2(float lo, float hi) {
    u64 r; asm("mov.b64 %0, {%1, %2};" : "=l"(r) : "f"(lo), "f"(hi)); return r;
}
__device__ __forceinline__ void unpk2(u64 v, float& lo, float& hi) {
    asm("mov.b64 {%0, %1}, %2;" : "=f"(lo), "=f"(hi) : "l"(v));
}
#define FMA2(d, a, b, c) asm("fma.rn.f32x2 %0, %1, %2, %3;" : "=l"(d) : "l"(a), "l"(b), "l"(c))
#define MUL2(d, a, b)    asm("mul.rn.f32x2 %0, %1, %2;"     : "=l"(d) : "l"(a), "l"(b))
#define ADD2(d, a, b)    asm("add.rn.f32x2 %0, %1, %2;"     : "=l"(d) : "l"(a), "l"(b))

// ---------------------------------------------------------------------------
// Kernel 1: fused downscale + gate + features.
// Block = 64 pixels x 4 k-slices (256 threads). grid = NIMG*NPIX/64 = 256.
// ---------------------------------------------------------------------------
__global__ __launch_bounds__(256) void prep_kernel(const float* __restrict__ images,
                                                   const float* __restrict__ segs,
                                                   const float* __restrict__ rois,
                                                   const int*   __restrict__ labels)
{
    __shared__ float pmax[4][64];
    int tid = threadIdx.x;
    int sub = tid >> 6;            // 0..3  k-slice
    int pp  = tid & 63;            // pixel within block
    int gp  = blockIdx.x * 64 + pp;   // global (n,p) flattened
    int n   = gp >> 12;
    int p   = gp & (NPIX - 1);
    int y = p >> 6, x = p & 63;
    int src = (2*y) * 128 + (2*x);

    float roi = rois[n * HW + src];

    const float* sb = segs + (size_t)n * KCH * HW + src;
    float mx = -1e30f;
    #pragma unroll
    for (int k = sub; k < KCH; k += 4) {
        const float* sp = sb + (size_t)k * HW;
        float2 t0 = *(const float2*)(sp);
        float2 t1 = *(const float2*)(sp + 128);
        float v = 0.25f * ((t0.x + t0.y) + (t1.x + t1.y));  // exact bilinear 2x
        mx = fmaxf(mx, v);
        g_sroi[n][k][p] = v * roi;
    }
    pmax[sub][pp] = mx;
    __syncthreads();

    if (sub == 0) {
        mx = fmaxf(fmaxf(pmax[0][pp], pmax[1][pp]), fmaxf(pmax[2][pp], pmax[3][pp]));
        int lbl = labels[n * HW + src];
        float gate = (lbl == 255) ? 1.0f : (roi - mx);
        g_gate[n][p] = fmaxf(gate, 0.0f);

        const float* ib = images + (size_t)n * 3 * HW + src;
        float fx = (float)x * (1.0f / 50.0f);   // SIGMA_XY * SCALE = 50
        float fy = (float)y * (1.0f / 50.0f);
        float r  = ib[0]      * (1.0f / 15.0f);
        float g  = ib[HW]     * (1.0f / 15.0f);
        float b  = ib[2 * HW] * (1.0f / 15.0f);
        g_feat[n][0][p] = fx; g_feat[n][1][p] = fy;
        g_feat[n][2][p] = r;  g_feat[n][3][p] = g; g_feat[n][4][p] = b;
        g_sq[n][p] = fx*fx + fy*fy + r*r + g*g + b*b;
    }
}

// ---------------------------------------------------------------------------
// Kernel 2: tiled bilateral energy over the upper triangle of (p,q) tiles.
// Thread (tx,ty): p_i = ty + 16*i (i=0..7), q pairs = 2*tx + 32*jj + {0,1}.
// All pairwise math in packed f32x2. Last CTA folds the final reduction.
// ---------------------------------------------------------------------------
__global__ __launch_bounds__(256, 2) void energy_kernel(float* __restrict__ out)
{
    __shared__ float sP[KCH][TILE], sQ[KCH][TILE];
    __shared__ float fP[5][TILE],  fQ[5][TILE];
    __shared__ float sqP[TILE], sqQ[TILE], gP[TILE], gQ[TILE];
    __shared__ float red[8];
    __shared__ int   lastflag;

    int t = blockIdx.x;
    int n = blockIdx.y;

    // triangular decode (uniform per block)
    int ti = 0, rem = t;
    while (rem >= NT - ti) { rem -= NT - ti; ti++; }
    int tj = ti + rem;
    int p0 = ti * TILE, q0 = tj * TILE;
    bool diag = (ti == tj);

    int tid = threadIdx.x;
    for (int i = tid; i < KCH * TILE; i += 256) {
        int k = i >> 7, pp = i & 127;
        sP[k][pp] = g_sroi[n][k][p0 + pp];
        sQ[k][pp] = g_sroi[n][k][q0 + pp];
    }
    for (int i = tid; i < 5 * TILE; i += 256) {
        int d = i >> 7, pp = i & 127;
        fP[d][pp] = g_feat[n][d][p0 + pp];
        fQ[d][pp] = g_feat[n][d][q0 + pp];
    }
    if (tid < TILE) {
        sqP[tid] = g_sq[n][p0 + tid];   sqQ[tid] = g_sq[n][q0 + tid];
        gP[tid]  = g_gate[n][p0 + tid]; gQ[tid]  = g_gate[n][q0 + tid];
    }
    __syncthreads();

    int tx = tid & 15, ty = tid >> 4;
    int qb = 2 * tx;                 // byte-pair base (element index)

    // ---- Phase 1: 5-D feature dot products (packed along q) ----
    u64 w2[8][4];
    #pragma unroll
    for (int i = 0; i < 8; i++)
        #pragma unroll
        for (int jj = 0; jj < 4; jj++) w2[i][jj] = 0ull;

    #pragma unroll
    for (int d = 0; d < 5; d++) {
        u64 bb[4];
        #pragma unroll
        for (int jj = 0; jj < 4; jj++)
            bb[jj] = *(const u64*)&fQ[d][qb + 32*jj];
        #pragma unroll
        for (int i = 0; i < 8; i++) {
            float a = fP[d][ty + 16*i];
            u64 aa = pk2(a, a);
            #pragma unroll
            for (int jj = 0; jj < 4; jj++) FMA2(w2[i][jj], aa, bb[jj], w2[i][jj]);
        }
    }

    // ---- Phase 2: w <- exp(-0.5*d2) * gate-coef, in place ----
    {
        u64 sq2[4], gq2[4];
        #pragma unroll
        for (int jj = 0; jj < 4; jj++) {
            sq2[jj] = *(const u64*)&sqQ[qb + 32*jj];
            gq2[jj] = *(const u64*)&gQ[qb + 32*jj];
        }
        u64 m2 = pk2(-2.0f, -2.0f);
        const float cexp = -0.72134752044f;   // -0.5 * log2(e)
        #pragma unroll
        for (int i = 0; i < 8; i++) {
            float sp = sqP[ty + 16*i], gpv = gP[ty + 16*i];
            u64 sp2 = pk2(sp, sp);
            u64 gp2 = pk2(gpv, gpv);
            #pragma unroll
            for (int jj = 0; jj < 4; jj++) {
                u64 s2; ADD2(s2, sp2, sq2[jj]);
                u64 d2; FMA2(d2, w2[i][jj], m2, s2);      // sp+sq-2*dot
                float dlo, dhi; unpk2(d2, dlo, dhi);
                float e0 = exp2f(fminf(dlo * cexp, 0.0f)); // clamp folds max(d2,0)
                float e1 = exp2f(fminf(dhi * cexp, 0.0f));
                u64 ee = pk2(e0, e1);
                u64 cf;
                if (diag) cf = gp2; else ADD2(cf, gp2, gq2[jj]);
                MUL2(w2[i][jj], ee, cf);
            }
        }
    }

    // ---- Phase 3: acc += a_i * (w_i . b), packed accumulator ----
    u64 acc2 = 0ull;
    #pragma unroll 3
    for (int k = 0; k < KCH; k++) {
        u64 bb[4];
        #pragma unroll
        for (int jj = 0; jj < 4; jj++)
            bb[jj] = *(const u64*)&sQ[k][qb + 32*jj];
        #pragma unroll
        for (int i = 0; i < 8; i++) {
            u64 in2;
            MUL2(in2, w2[i][0], bb[0]);
            FMA2(in2, w2[i][1], bb[1], in2);
            FMA2(in2, w2[i][2], bb[2], in2);
            FMA2(in2, w2[i][3], bb[3], in2);
            float a = sP[k][ty + 16*i];
            u64 aa = pk2(a, a);
            FMA2(acc2, aa, in2, acc2);
        }
    }
    float alo, ahi; unpk2(acc2, alo, ahi);
    float acc = alo + ahi;

    // ---- block reduction, deterministic per-CTA partial ----
    #pragma unroll
    for (int o = 16; o > 0; o >>= 1) acc += __shfl_down_sync(0xffffffffu, acc, o);
    if ((tid & 31) == 0) red[tid >> 5] = acc;
    __syncthreads();
    if (tid == 0) {
        float s = 0.0f;
        #pragma unroll
        for (int v = 0; v < 8; v++) s += red[v];
        g_partial[n * NPAIR + t] = s;
        __threadfence();
        int v = atomicAdd(&g_ctr, 1);
        lastflag = (v == NIMG * NPAIR - 1);
    }
    __syncthreads();

    // ---- last CTA: deterministic final reduction + scaling ----
    if (lastflag) {
        float s = 0.0f;
        for (int i = tid; i < NIMG * NPAIR; i += 256) s += g_partial[i];
        #pragma unroll
        for (int o = 16; o > 0; o >>= 1) s += __shfl_down_sync(0xffffffffu, s, o);
        if ((tid & 31) == 0) red[tid >> 5] = s;
        __syncthreads();
        if (tid == 0) {
            float tot = 0.0f;
            #pragma unroll
            for (int v = 0; v < 8; v++) tot += red[v];
            out[0] = tot * (-1e-7f / (float)NIMG);   // WEIGHT * (-sum / N)
            g_ctr = 0;                                // reset for graph replay
        }
    }
}

// ---------------------------------------------------------------------------
extern "C" void kernel_launch(void* const* d_in, const int* in_sizes, int n_in,
                              void* d_out, int out_size)
{
    const float* images = (const float*)d_in[0];   // [4,3,128,128]
    const float* segs   = (const float*)d_in[1];   // [4,21,128,128]
    const float* rois   = (const float*)d_in[2];   // [4,128,128]
    const int*   labels = (const int*)  d_in[3];   // [4,1,128,128]

    prep_kernel<<<NIMG * NPIX / 64, 256>>>(images, segs, rois, labels);
    dim3 grid(NPAIR, NIMG);
    energy_kernel<<<grid, 256>>>((float*)d_out);
}

// round 3
// speedup vs baseline: 1.5384x; 1.5384x over previous
#include <cuda_runtime.h>

#define NIMG  4
#define KCH   21
#define NPIX  4096      // 64*64
#define TILE  128
#define NT    32        // NPIX / TILE
#define NPAIR 528       // NT*(NT+1)/2
#define HW    16384     // 128*128

typedef unsigned long long u64;

// Scratch (device globals; no allocation in kernel_launch)
__device__ float g_sroi[NIMG][KCH][NPIX];   // seg (2x2 avg) * roi
__device__ float g_feat[NIMG][5][NPIX];     // x/50, y/50, r/15, g/15, b/15
__device__ float g_sq  [NIMG][NPIX];        // |f|^2
__device__ float g_gate[NIMG][NPIX];
__device__ float g_partial[NIMG * NPAIR];
__device__ int   g_ctr;                     // zero-init; reset by last block

// ---- packed f32x2 helpers (sm_103a dual-pumped FP32) ----
__device__ __forceinline__ u64 pk2(float lo, float hi) {
    u64 r; asm("mov.b64 %0, {%1, %2};" : "=l"(r) : "f"(lo), "f"(hi)); return r;
}
__device__ __forceinline__ void unpk2(u64 v, float& lo, float& hi) {
    asm("mov.b64 {%0, %1}, %2;" : "=f"(lo), "=f"(hi) : "l"(v));
}
#define FMA2(d, a, b, c) asm("fma.rn.f32x2 %0, %1, %2, %3;" : "=l"(d) : "l"(a), "l"(b), "l"(c))
#define MUL2(d, a, b)    asm("mul.rn.f32x2 %0, %1, %2;"     : "=l"(d) : "l"(a), "l"(b))
#define ADD2(d, a, b)    asm("add.rn.f32x2 %0, %1, %2;"     : "=l"(d) : "l"(a), "l"(b))

// ---------------------------------------------------------------------------
// Kernel 1: fused downscale + gate + features.
// Block = 64 pixels x 4 k-slices (256 threads). grid = NIMG*NPIX/64 = 256.
// ---------------------------------------------------------------------------
__global__ __launch_bounds__(256) void prep_kernel(const float* __restrict__ images,
                                                   const float* __restrict__ segs,
                                                   const float* __restrict__ rois,
                                                   const int*   __restrict__ labels)
{
    __shared__ float pmax[4][64];
    int tid = threadIdx.x;
    int sub = tid >> 6;            // 0..3  k-slice
    int pp  = tid & 63;            // pixel within block
    int gp  = blockIdx.x * 64 + pp;   // global (n,p) flattened
    int n   = gp >> 12;
    int p   = gp & (NPIX - 1);
    int y = p >> 6, x = p & 63;
    int src = (2*y) * 128 + (2*x);

    float roi = rois[n * HW + src];

    const float* sb = segs + (size_t)n * KCH * HW + src;
    float mx = -1e30f;
    #pragma unroll
    for (int k = sub; k < KCH; k += 4) {
        const float* sp = sb + (size_t)k * HW;
        float2 t0 = *(const float2*)(sp);
        float2 t1 = *(const float2*)(sp + 128);
        float v = 0.25f * ((t0.x + t0.y) + (t1.x + t1.y));  // exact bilinear 2x
        mx = fmaxf(mx, v);
        g_sroi[n][k][p] = v * roi;
    }
    pmax[sub][pp] = mx;
    __syncthreads();

    if (sub == 0) {
        mx = fmaxf(fmaxf(pmax[0][pp], pmax[1][pp]), fmaxf(pmax[2][pp], pmax[3][pp]));
        int lbl = labels[n * HW + src];
        float gate = (lbl == 255) ? 1.0f : (roi - mx);
        g_gate[n][p] = fmaxf(gate, 0.0f);

        const float* ib = images + (size_t)n * 3 * HW + src;
        float fx = (float)x * (1.0f / 50.0f);   // SIGMA_XY * SCALE = 50
        float fy = (float)y * (1.0f / 50.0f);
        float r  = ib[0]      * (1.0f / 15.0f);
        float g  = ib[HW]     * (1.0f / 15.0f);
        float b  = ib[2 * HW] * (1.0f / 15.0f);
        g_feat[n][0][p] = fx; g_feat[n][1][p] = fy;
        g_feat[n][2][p] = r;  g_feat[n][3][p] = g; g_feat[n][4][p] = b;
        g_sq[n][p] = fx*fx + fy*fy + r*r + g*g + b*b;
    }
}

// ---------------------------------------------------------------------------
// Kernel 2: tiled bilateral energy over the upper triangle of (p,q) tiles.
// Thread (tx,ty): p_i = ty + 16*i (i=0..7), q pairs = 2*tx + 32*jj + {0,1}.
// All pairwise math in packed f32x2. Last CTA folds the final reduction.
// ---------------------------------------------------------------------------
__global__ __launch_bounds__(256, 2) void energy_kernel(float* __restrict__ out)
{
    __shared__ float sP[KCH][TILE], sQ[KCH][TILE];
    __shared__ float fP[5][TILE],  fQ[5][TILE];
    __shared__ float sqP[TILE], sqQ[TILE], gP[TILE], gQ[TILE];
    __shared__ float red[8];
    __shared__ int   lastflag;

    int t = blockIdx.x;
    int n = blockIdx.y;

    // triangular decode (uniform per block)
    int ti = 0, rem = t;
    while (rem >= NT - ti) { rem -= NT - ti; ti++; }
    int tj = ti + rem;
    int p0 = ti * TILE, q0 = tj * TILE;
    bool diag = (ti == tj);

    int tid = threadIdx.x;
    for (int i = tid; i < KCH * TILE; i += 256) {
        int k = i >> 7, pp = i & 127;
        sP[k][pp] = g_sroi[n][k][p0 + pp];
        sQ[k][pp] = g_sroi[n][k][q0 + pp];
    }
    for (int i = tid; i < 5 * TILE; i += 256) {
        int d = i >> 7, pp = i & 127;
        fP[d][pp] = g_feat[n][d][p0 + pp];
        fQ[d][pp] = g_feat[n][d][q0 + pp];
    }
    if (tid < TILE) {
        sqP[tid] = g_sq[n][p0 + tid];   sqQ[tid] = g_sq[n][q0 + tid];
        gP[tid]  = g_gate[n][p0 + tid]; gQ[tid]  = g_gate[n][q0 + tid];
    }
    __syncthreads();

    int tx = tid & 15, ty = tid >> 4;
    int qb = 2 * tx;                 // byte-pair base (element index)

    // ---- Phase 1: 5-D feature dot products (packed along q) ----
    u64 w2[8][4];
    #pragma unroll
    for (int i = 0; i < 8; i++)
        #pragma unroll
        for (int jj = 0; jj < 4; jj++) w2[i][jj] = 0ull;

    #pragma unroll
    for (int d = 0; d < 5; d++) {
        u64 bb[4];
        #pragma unroll
        for (int jj = 0; jj < 4; jj++)
            bb[jj] = *(const u64*)&fQ[d][qb + 32*jj];
        #pragma unroll
        for (int i = 0; i < 8; i++) {
            float a = fP[d][ty + 16*i];
            u64 aa = pk2(a, a);
            #pragma unroll
            for (int jj = 0; jj < 4; jj++) FMA2(w2[i][jj], aa, bb[jj], w2[i][jj]);
        }
    }

    // ---- Phase 2: w <- exp(-0.5*d2) * gate-coef, in place ----
    {
        u64 sq2[4], gq2[4];
        #pragma unroll
        for (int jj = 0; jj < 4; jj++) {
            sq2[jj] = *(const u64*)&sqQ[qb + 32*jj];
            gq2[jj] = *(const u64*)&gQ[qb + 32*jj];
        }
        u64 m2 = pk2(-2.0f, -2.0f);
        const float cexp = -0.72134752044f;   // -0.5 * log2(e)
        #pragma unroll
        for (int i = 0; i < 8; i++) {
            float sp = sqP[ty + 16*i], gpv = gP[ty + 16*i];
            u64 sp2 = pk2(sp, sp);
            u64 gp2 = pk2(gpv, gpv);
            #pragma unroll
            for (int jj = 0; jj < 4; jj++) {
                u64 s2; ADD2(s2, sp2, sq2[jj]);
                u64 d2; FMA2(d2, w2[i][jj], m2, s2);      // sp+sq-2*dot
                float dlo, dhi; unpk2(d2, dlo, dhi);
                float e0 = exp2f(fminf(dlo * cexp, 0.0f)); // clamp folds max(d2,0)
                float e1 = exp2f(fminf(dhi * cexp, 0.0f));
                u64 ee = pk2(e0, e1);
                u64 cf;
                if (diag) cf = gp2; else ADD2(cf, gp2, gq2[jj]);
                MUL2(w2[i][jj], ee, cf);
            }
        }
    }

    // ---- Phase 3: acc += a_i * (w_i . b), packed accumulator ----
    u64 acc2 = 0ull;
    #pragma unroll 3
    for (int k = 0; k < KCH; k++) {
        u64 bb[4];
        #pragma unroll
        for (int jj = 0; jj < 4; jj++)
            bb[jj] = *(const u64*)&sQ[k][qb + 32*jj];
        #pragma unroll
        for (int i = 0; i < 8; i++) {
            u64 in2;
            MUL2(in2, w2[i][0], bb[0]);
            FMA2(in2, w2[i][1], bb[1], in2);
            FMA2(in2, w2[i][2], bb[2], in2);
            FMA2(in2, w2[i][3], bb[3], in2);
            float a = sP[k][ty + 16*i];
            u64 aa = pk2(a, a);
            FMA2(acc2, aa, in2, acc2);
        }
    }
    float alo, ahi; unpk2(acc2, alo, ahi);
    float acc = alo + ahi;

    // ---- block reduction, deterministic per-CTA partial ----
    #pragma unroll
    for (int o = 16; o > 0; o >>= 1) acc += __shfl_down_sync(0xffffffffu, acc, o);
    if ((tid & 31) == 0) red[tid >> 5] = acc;
    __syncthreads();
    if (tid == 0) {
        float s = 0.0f;
        #pragma unroll
        for (int v = 0; v < 8; v++) s += red[v];
        g_partial[n * NPAIR + t] = s;
        __threadfence();
        int v = atomicAdd(&g_ctr, 1);
        lastflag = (v == NIMG * NPAIR - 1);
    }
    __syncthreads();

    // ---- last CTA: deterministic final reduction + scaling ----
    if (lastflag) {
        float s = 0.0f;
        for (int i = tid; i < NIMG * NPAIR; i += 256) s += g_partial[i];
        #pragma unroll
        for (int o = 16; o > 0; o >>= 1) s += __shfl_down_sync(0xffffffffu, s, o);
        if ((tid & 31) == 0) red[tid >> 5] = s;
        __syncthreads();
        if (tid == 0) {
            float tot = 0.0f;
            #pragma unroll
            for (int v = 0; v < 8; v++) tot += red[v];
            out[0] = tot * (-1e-7f / (float)NIMG);   // WEIGHT * (-sum / N)
            g_ctr = 0;                                // reset for graph replay
        }
    }
}

// ---------------------------------------------------------------------------
extern "C" void kernel_launch(void* const* d_in, const int* in_sizes, int n_in,
                              void* d_out, int out_size)
{
    const float* images = (const float*)d_in[0];   // [4,3,128,128]
    const float* segs   = (const float*)d_in[1];   // [4,21,128,128]
    const float* rois   = (const float*)d_in[2];   // [4,128,128]
    const int*   labels = (const int*)  d_in[3];   // [4,1,128,128]

    prep_kernel<<<NIMG * NPIX / 64, 256>>>(images, segs, rois, labels);
    dim3 grid(NPAIR, NIMG);
    energy_kernel<<<grid, 256>>>((float*)d_out);
}

// round 4
// speedup vs baseline: 1.5413x; 1.0019x over previous
#include <cuda_runtime.h>

#define NIMG  4
#define KCH   21
#define NPIX  4096      // 64*64
#define TILE  128
#define NT    32        // NPIX / TILE
#define NPAIR 528       // NT*(NT+1)/2
#define HW    16384     // 128*128

typedef unsigned long long u64;

// Scratch (device globals; no allocation in kernel_launch)
__device__ float g_sroi[NIMG][KCH][NPIX];   // seg (2x2 avg) * roi
__device__ float g_feat[NIMG][5][NPIX];     // x/50, y/50, r/15, g/15, b/15
__device__ float g_sq  [NIMG][NPIX];        // |f|^2
__device__ float g_gate[NIMG][NPIX];
__device__ float g_partial[NIMG * NPAIR];
__device__ int   g_ctr;                     // zero-init; reset by last block

// ---- packed f32x2 helpers (sm_103a dual-pumped FP32) ----
__device__ __forceinline__ u64 pk2(float lo, float hi) {
    u64 r; asm("mov.b64 %0, {%1, %2};" : "=l"(r) : "f"(lo), "f"(hi)); return r;
}
__device__ __forceinline__ void unpk2(u64 v, float& lo, float& hi) {
    asm("mov.b64 {%0, %1}, %2;" : "=f"(lo), "=f"(hi) : "l"(v));
}
#define FMA2(d, a, b, c) asm("fma.rn.f32x2 %0, %1, %2, %3;" : "=l"(d) : "l"(a), "l"(b), "l"(c))
#define MUL2(d, a, b)    asm("mul.rn.f32x2 %0, %1, %2;"     : "=l"(d) : "l"(a), "l"(b))
#define ADD2(d, a, b)    asm("add.rn.f32x2 %0, %1, %2;"     : "=l"(d) : "l"(a), "l"(b))

// ---------------------------------------------------------------------------
// Kernel 1: fused downscale + gate + features.
// Block = 64 pixels x 4 k-slices (256 threads). grid = NIMG*NPIX/64 = 256.
// ---------------------------------------------------------------------------
__global__ __launch_bounds__(256) void prep_kernel(const float* __restrict__ images,
                                                   const float* __restrict__ segs,
                                                   const float* __restrict__ rois,
                                                   const int*   __restrict__ labels)
{
    __shared__ float pmax[4][64];
    int tid = threadIdx.x;
    int sub = tid >> 6;            // 0..3  k-slice
    int pp  = tid & 63;            // pixel within block
    int gp  = blockIdx.x * 64 + pp;   // global (n,p) flattened
    int n   = gp >> 12;
    int p   = gp & (NPIX - 1);
    int y = p >> 6, x = p & 63;
    int src = (2*y) * 128 + (2*x);

    float roi = rois[n * HW + src];

    const float* sb = segs + (size_t)n * KCH * HW + src;
    float mx = -1e30f;
    #pragma unroll
    for (int k = sub; k < KCH; k += 4) {
        const float* sp = sb + (size_t)k * HW;
        float2 t0 = *(const float2*)(sp);
        float2 t1 = *(const float2*)(sp + 128);
        float v = 0.25f * ((t0.x + t0.y) + (t1.x + t1.y));  // exact bilinear 2x
        mx = fmaxf(mx, v);
        g_sroi[n][k][p] = v * roi;
    }
    pmax[sub][pp] = mx;
    __syncthreads();

    if (sub == 0) {
        mx = fmaxf(fmaxf(pmax[0][pp], pmax[1][pp]), fmaxf(pmax[2][pp], pmax[3][pp]));
        int lbl = labels[n * HW + src];
        float gate = (lbl == 255) ? 1.0f : (roi - mx);
        g_gate[n][p] = fmaxf(gate, 0.0f);

        const float* ib = images + (size_t)n * 3 * HW + src;
        float fx = (float)x * (1.0f / 50.0f);   // SIGMA_XY * SCALE = 50
        float fy = (float)y * (1.0f / 50.0f);
        float r  = ib[0]      * (1.0f / 15.0f);
        float g  = ib[HW]     * (1.0f / 15.0f);
        float b  = ib[2 * HW] * (1.0f / 15.0f);
        g_feat[n][0][p] = fx; g_feat[n][1][p] = fy;
        g_feat[n][2][p] = r;  g_feat[n][3][p] = g; g_feat[n][4][p] = b;
        g_sq[n][p] = fx*fx + fy*fy + r*r + g*g + b*b;
    }
}

// ---------------------------------------------------------------------------
// Kernel 2: tiled bilateral energy over the upper triangle of (p,q) tiles.
// Thread (tx,ty): p_i = ty + 16*i (i=0..7), q pairs = 2*tx + 32*jj + {0,1}.
// All pairwise math in packed f32x2. Last CTA folds the final reduction.
// ---------------------------------------------------------------------------
__global__ __launch_bounds__(256, 2) void energy_kernel(float* __restrict__ out)
{
    __shared__ float sP[KCH][TILE], sQ[KCH][TILE];
    __shared__ float fP[5][TILE],  fQ[5][TILE];
    __shared__ float sqP[TILE], sqQ[TILE], gP[TILE], gQ[TILE];
    __shared__ float red[8];
    __shared__ int   lastflag;

    int t = blockIdx.x;
    int n = blockIdx.y;

    // triangular decode (uniform per block)
    int ti = 0, rem = t;
    while (rem >= NT - ti) { rem -= NT - ti; ti++; }
    int tj = ti + rem;
    int p0 = ti * TILE, q0 = tj * TILE;
    bool diag = (ti == tj);

    int tid = threadIdx.x;
    for (int i = tid; i < KCH * TILE; i += 256) {
        int k = i >> 7, pp = i & 127;
        sP[k][pp] = g_sroi[n][k][p0 + pp];
        sQ[k][pp] = g_sroi[n][k][q0 + pp];
    }
    for (int i = tid; i < 5 * TILE; i += 256) {
        int d = i >> 7, pp = i & 127;
        fP[d][pp] = g_feat[n][d][p0 + pp];
        fQ[d][pp] = g_feat[n][d][q0 + pp];
    }
    if (tid < TILE) {
        sqP[tid] = g_sq[n][p0 + tid];   sqQ[tid] = g_sq[n][q0 + tid];
        gP[tid]  = g_gate[n][p0 + tid]; gQ[tid]  = g_gate[n][q0 + tid];
    }
    __syncthreads();

    int tx = tid & 15, ty = tid >> 4;
    int qb = 2 * tx;                 // byte-pair base (element index)

    // ---- Phase 1: 5-D feature dot products (packed along q) ----
    u64 w2[8][4];
    #pragma unroll
    for (int i = 0; i < 8; i++)
        #pragma unroll
        for (int jj = 0; jj < 4; jj++) w2[i][jj] = 0ull;

    #pragma unroll
    for (int d = 0; d < 5; d++) {
        u64 bb[4];
        #pragma unroll
        for (int jj = 0; jj < 4; jj++)
            bb[jj] = *(const u64*)&fQ[d][qb + 32*jj];
        #pragma unroll
        for (int i = 0; i < 8; i++) {
            float a = fP[d][ty + 16*i];
            u64 aa = pk2(a, a);
            #pragma unroll
            for (int jj = 0; jj < 4; jj++) FMA2(w2[i][jj], aa, bb[jj], w2[i][jj]);
        }
    }

    // ---- Phase 2: w <- exp(-0.5*d2) * gate-coef, in place ----
    {
        u64 sq2[4], gq2[4];
        #pragma unroll
        for (int jj = 0; jj < 4; jj++) {
            sq2[jj] = *(const u64*)&sqQ[qb + 32*jj];
            gq2[jj] = *(const u64*)&gQ[qb + 32*jj];
        }
        u64 m2 = pk2(-2.0f, -2.0f);
        const float cexp = -0.72134752044f;   // -0.5 * log2(e)
        #pragma unroll
        for (int i = 0; i < 8; i++) {
            float sp = sqP[ty + 16*i], gpv = gP[ty + 16*i];
            u64 sp2 = pk2(sp, sp);
            u64 gp2 = pk2(gpv, gpv);
            #pragma unroll
            for (int jj = 0; jj < 4; jj++) {
                u64 s2; ADD2(s2, sp2, sq2[jj]);
                u64 d2; FMA2(d2, w2[i][jj], m2, s2);      // sp+sq-2*dot
                float dlo, dhi; unpk2(d2, dlo, dhi);
                float e0 = exp2f(fminf(dlo * cexp, 0.0f)); // clamp folds max(d2,0)
                float e1 = exp2f(fminf(dhi * cexp, 0.0f));
                u64 ee = pk2(e0, e1);
                u64 cf;
                if (diag) cf = gp2; else ADD2(cf, gp2, gq2[jj]);
                MUL2(w2[i][jj], ee, cf);
            }
        }
    }

    // ---- Phase 3: acc += a_i * (w_i . b), packed accumulator ----
    u64 acc2 = 0ull;
    #pragma unroll 3
    for (int k = 0; k < KCH; k++) {
        u64 bb[4];
        #pragma unroll
        for (int jj = 0; jj < 4; jj++)
            bb[jj] = *(const u64*)&sQ[k][qb + 32*jj];
        #pragma unroll
        for (int i = 0; i < 8; i++) {
            u64 in2;
            MUL2(in2, w2[i][0], bb[0]);
            FMA2(in2, w2[i][1], bb[1], in2);
            FMA2(in2, w2[i][2], bb[2], in2);
            FMA2(in2, w2[i][3], bb[3], in2);
            float a = sP[k][ty + 16*i];
            u64 aa = pk2(a, a);
            FMA2(acc2, aa, in2, acc2);
        }
    }
    float alo, ahi; unpk2(acc2, alo, ahi);
    float acc = alo + ahi;

    // ---- block reduction, deterministic per-CTA partial ----
    #pragma unroll
    for (int o = 16; o > 0; o >>= 1) acc += __shfl_down_sync(0xffffffffu, acc, o);
    if ((tid & 31) == 0) red[tid >> 5] = acc;
    __syncthreads();
    if (tid == 0) {
        float s = 0.0f;
        #pragma unroll
        for (int v = 0; v < 8; v++) s += red[v];
        g_partial[n * NPAIR + t] = s;
        __threadfence();
        int v = atomicAdd(&g_ctr, 1);
        lastflag = (v == NIMG * NPAIR - 1);
    }
    __syncthreads();

    // ---- last CTA: deterministic final reduction + scaling ----
    if (lastflag) {
        float s = 0.0f;
        for (int i = tid; i < NIMG * NPAIR; i += 256) s += g_partial[i];
        #pragma unroll
        for (int o = 16; o > 0; o >>= 1) s += __shfl_down_sync(0xffffffffu, s, o);
        if ((tid & 31) == 0) red[tid >> 5] = s;
        __syncthreads();
        if (tid == 0) {
            float tot = 0.0f;
            #pragma unroll
            for (int v = 0; v < 8; v++) tot += red[v];
            out[0] = tot * (-1e-7f / (float)NIMG);   // WEIGHT * (-sum / N)
            g_ctr = 0;                                // reset for graph replay
        }
    }
}

// ---------------------------------------------------------------------------
extern "C" void kernel_launch(void* const* d_in, const int* in_sizes, int n_in,
                              void* d_out, int out_size)
{
    const float* images = (const float*)d_in[0];   // [4,3,128,128]
    const float* segs   = (const float*)d_in[1];   // [4,21,128,128]
    const float* rois   = (const float*)d_in[2];   // [4,128,128]
    const int*   labels = (const int*)  d_in[3];   // [4,1,128,128]

    prep_kernel<<<NIMG * NPIX / 64, 256>>>(images, segs, rois, labels);
    dim3 grid(NPAIR, NIMG);
    energy_kernel<<<grid, 256>>>((float*)d_out);
}

// round 5
// speedup vs baseline: 1.6657x; 1.0807x over previous
#include <cuda_runtime.h>

#define NIMG  4
#define KCH   21
#define NPIX  4096      // 64*64
#define TILE  128
#define NT    32        // NPIX / TILE
#define NPAIR 528       // NT*(NT+1)/2
#define HW    16384     // 128*128

typedef unsigned long long u64;

// Scratch (device globals; no allocation in kernel_launch)
__device__ float g_sroi[NIMG][KCH][NPIX];   // seg (2x2 avg) * roi
__device__ float g_feat[NIMG][5][NPIX];     // x/50, y/50, r/15, g/15, b/15
__device__ float g_sqs [NIMG][NPIX];        // cexp * |f|^2   (pre-scaled!)
__device__ float g_gate[NIMG][NPIX];
__device__ float g_partial[NIMG * NPAIR];
__device__ int   g_ctr;                     // zero-init; reset by last block

#define CEXP  (-0.72134752044448170f)       // -0.5 * log2(e)
#define LOG2E ( 1.44269504088896340f)       //  -2 * CEXP

// ---- packed f32x2 helpers ----
__device__ __forceinline__ u64 pk2(float lo, float hi) {
    u64 r; asm("mov.b64 %0, {%1, %2};" : "=l"(r) : "f"(lo), "f"(hi)); return r;
}
__device__ __forceinline__ void unpk2(u64 v, float& lo, float& hi) {
    asm("mov.b64 {%0, %1}, %2;" : "=f"(lo), "=f"(hi) : "l"(v));
}
#define FMA2(d, a, b, c) asm("fma.rn.f32x2 %0, %1, %2, %3;" : "=l"(d) : "l"(a), "l"(b), "l"(c))
#define MUL2(d, a, b)    asm("mul.rn.f32x2 %0, %1, %2;"     : "=l"(d) : "l"(a), "l"(b))
#define ADD2(d, a, b)    asm("add.rn.f32x2 %0, %1, %2;"     : "=l"(d) : "l"(a), "l"(b))

// ---------------------------------------------------------------------------
// Kernel 1: fused downscale + gate + features.
// Block = 64 pixels x 4 k-slices (256 threads). grid = NIMG*NPIX/64 = 256.
// ---------------------------------------------------------------------------
__global__ __launch_bounds__(256) void prep_kernel(const float* __restrict__ images,
                                                   const float* __restrict__ segs,
                                                   const float* __restrict__ rois,
                                                   const int*   __restrict__ labels)
{
    __shared__ float pmax[4][64];
    int tid = threadIdx.x;
    int sub = tid >> 6;            // 0..3  k-slice
    int pp  = tid & 63;            // pixel within block
    int gp  = blockIdx.x * 64 + pp;   // global (n,p) flattened
    int n   = gp >> 12;
    int p   = gp & (NPIX - 1);
    int y = p >> 6, x = p & 63;
    int src = (2*y) * 128 + (2*x);

    float roi = rois[n * HW + src];

    const float* sb = segs + (size_t)n * KCH * HW + src;
    float mx = -1e30f;
    #pragma unroll
    for (int k = sub; k < KCH; k += 4) {
        const float* sp = sb + (size_t)k * HW;
        float2 t0 = *(const float2*)(sp);
        float2 t1 = *(const float2*)(sp + 128);
        float v = 0.25f * ((t0.x + t0.y) + (t1.x + t1.y));  // exact bilinear 2x
        mx = fmaxf(mx, v);
        g_sroi[n][k][p] = v * roi;
    }
    pmax[sub][pp] = mx;
    __syncthreads();

    if (sub == 0) {
        mx = fmaxf(fmaxf(pmax[0][pp], pmax[1][pp]), fmaxf(pmax[2][pp], pmax[3][pp]));
        int lbl = labels[n * HW + src];
        float gate = (lbl == 255) ? 1.0f : (roi - mx);
        g_gate[n][p] = fmaxf(gate, 0.0f);

        const float* ib = images + (size_t)n * 3 * HW + src;
        float fx = (float)x * (1.0f / 50.0f);   // SIGMA_XY * SCALE = 50
        float fy = (float)y * (1.0f / 50.0f);
        float r  = ib[0]      * (1.0f / 15.0f);
        float g  = ib[HW]     * (1.0f / 15.0f);
        float b  = ib[2 * HW] * (1.0f / 15.0f);
        g_feat[n][0][p] = fx; g_feat[n][1][p] = fy;
        g_feat[n][2][p] = r;  g_feat[n][3][p] = g; g_feat[n][4][p] = b;
        g_sqs[n][p] = CEXP * (fx*fx + fy*fy + r*r + g*g + b*b);
    }
}

// ---------------------------------------------------------------------------
// Kernel 2: tiled bilateral energy, 128x128 tile per CTA, 512 threads.
// Thread (tx 0..15, ty 0..31): p_i = ty + 32*i (i=0..3, warp-broadcast loads),
// q pairs = 2*tx + 32*jj + {0,1} (jj=0..3, LDS.64 conflict-free).
// All pairwise math packed f32x2. Last CTA folds the final reduction.
// ---------------------------------------------------------------------------
__global__ __launch_bounds__(512, 2) void energy_kernel(float* __restrict__ out)
{
    __shared__ float sP[KCH][TILE], sQ[KCH][TILE];
    __shared__ float fP[5][TILE],  fQ[5][TILE];
    __shared__ float sqP[TILE], sqQ[TILE], gP[TILE], gQ[TILE];
    __shared__ float red[16];
    __shared__ int   lastflag;

    int t = blockIdx.x;
    int n = blockIdx.y;

    // triangular decode (uniform per block)
    int ti = 0, rem = t;
    while (rem >= NT - ti) { rem -= NT - ti; ti++; }
    int tj = ti + rem;
    int p0 = ti * TILE, q0 = tj * TILE;
    bool diag = (ti == tj);

    int tid = threadIdx.x;
    for (int i = tid; i < KCH * TILE; i += 512) {
        int k = i >> 7, pp = i & 127;
        sP[k][pp] = g_sroi[n][k][p0 + pp];
        sQ[k][pp] = g_sroi[n][k][q0 + pp];
    }
    for (int i = tid; i < 5 * TILE; i += 512) {
        int d = i >> 7, pp = i & 127;
        fP[d][pp] = g_feat[n][d][p0 + pp];
        fQ[d][pp] = g_feat[n][d][q0 + pp];
    }
    if (tid < TILE) {
        sqP[tid] = g_sqs[n][p0 + tid];  sqQ[tid] = g_sqs[n][q0 + tid];
        gP[tid]  = g_gate[n][p0 + tid]; gQ[tid]  = g_gate[n][q0 + tid];
    }
    __syncthreads();

    int tx = tid & 15, ty = tid >> 4;   // ty 0..31
    int qb = 2 * tx;

    // ---- Phase 1: 5-D feature dot products (packed along q) ----
    u64 w2[4][4];
    #pragma unroll
    for (int i = 0; i < 4; i++)
        #pragma unroll
        for (int jj = 0; jj < 4; jj++) w2[i][jj] = 0ull;

    #pragma unroll
    for (int d = 0; d < 5; d++) {
        u64 bb[4];
        #pragma unroll
        for (int jj = 0; jj < 4; jj++)
            bb[jj] = *(const u64*)&fQ[d][qb + 32*jj];
        #pragma unroll
        for (int i = 0; i < 4; i++) {
            float a = fP[d][ty + 32*i];
            u64 aa = pk2(a, a);
            #pragma unroll
            for (int jj = 0; jj < 4; jj++) FMA2(w2[i][jj], aa, bb[jj], w2[i][jj]);
        }
    }

    // ---- Phase 2: w <- exp2(min(sps+sqs+log2e*w, 0)) * gate-coef, in place ----
    {
        u64 l2e = pk2(LOG2E, LOG2E);
        #pragma unroll
        for (int jj = 0; jj < 4; jj++) {
            u64 sqs2 = *(const u64*)&sqQ[qb + 32*jj];
            u64 gq2  = *(const u64*)&gQ[qb + 32*jj];
            #pragma unroll
            for (int i = 0; i < 4; i++) {
                float sp = sqP[ty + 32*i];
                float gpv = gP[ty + 32*i];
                u64 s2; ADD2(s2, pk2(sp, sp), sqs2);
                u64 t2; FMA2(t2, w2[i][jj], l2e, s2);
                float tlo, thi; unpk2(t2, tlo, thi);
                float e0 = exp2f(fminf(tlo, 0.0f));   // clamp folds max(d2,0)
                float e1 = exp2f(fminf(thi, 0.0f));
                u64 ee = pk2(e0, e1);
                u64 gp2 = pk2(gpv, gpv);
                u64 cf;
                if (diag) cf = gp2; else ADD2(cf, gp2, gq2);
                MUL2(w2[i][jj], ee, cf);
            }
        }
    }

    // ---- Phase 3: acc += a_i * (w_i . b), packed, dual accumulators ----
    u64 accA = 0ull, accB = 0ull;
    #pragma unroll 3
    for (int k = 0; k < KCH; k++) {
        u64 bb[4];
        #pragma unroll
        for (int jj = 0; jj < 4; jj++)
            bb[jj] = *(const u64*)&sQ[k][qb + 32*jj];
        #pragma unroll
        for (int i = 0; i < 4; i++) {
            u64 in2;
            MUL2(in2, w2[i][0], bb[0]);
            FMA2(in2, w2[i][1], bb[1], in2);
            FMA2(in2, w2[i][2], bb[2], in2);
            FMA2(in2, w2[i][3], bb[3], in2);
            float a = sP[k][ty + 32*i];
            u64 aa = pk2(a, a);
            if (i & 1) { FMA2(accB, aa, in2, accB); }
            else       { FMA2(accA, aa, in2, accA); }
        }
    }
    u64 acc2; ADD2(acc2, accA, accB);
    float alo, ahi; unpk2(acc2, alo, ahi);
    float acc = alo + ahi;

    // ---- block reduction, deterministic per-CTA partial ----
    #pragma unroll
    for (int o = 16; o > 0; o >>= 1) acc += __shfl_down_sync(0xffffffffu, acc, o);
    if ((tid & 31) == 0) red[tid >> 5] = acc;
    __syncthreads();
    if (tid == 0) {
        float s = 0.0f;
        #pragma unroll
        for (int v = 0; v < 16; v++) s += red[v];
        g_partial[n * NPAIR + t] = s;
        __threadfence();
        int v = atomicAdd(&g_ctr, 1);
        lastflag = (v == NIMG * NPAIR - 1);
    }
    __syncthreads();

    // ---- last CTA: deterministic final reduction + scaling ----
    if (lastflag) {
        float s = 0.0f;
        for (int i = tid; i < NIMG * NPAIR; i += 512) s += g_partial[i];
        #pragma unroll
        for (int o = 16; o > 0; o >>= 1) s += __shfl_down_sync(0xffffffffu, s, o);
        if ((tid & 31) == 0) red[tid >> 5] = s;
        __syncthreads();
        if (tid == 0) {
            float tot = 0.0f;
            #pragma unroll
            for (int v = 0; v < 16; v++) tot += red[v];
            out[0] = tot * (-1e-7f / (float)NIMG);   // WEIGHT * (-sum / N)
            g_ctr = 0;                                // reset for graph replay
        }
    }
}

// ---------------------------------------------------------------------------
extern "C" void kernel_launch(void* const* d_in, const int* in_sizes, int n_in,
                              void* d_out, int out_size)
{
    const float* images = (const float*)d_in[0];   // [4,3,128,128]
    const float* segs   = (const float*)d_in[1];   // [4,21,128,128]
    const float* rois   = (const float*)d_in[2];   // [4,128,128]
    const int*   labels = (const int*)  d_in[3];   // [4,1,128,128]

    prep_kernel<<<NIMG * NPIX / 64, 256>>>(images, segs, rois, labels);
    dim3 grid(NPAIR, NIMG);
    energy_kernel<<<grid, 512>>>((float*)d_out);
}

// round 7
// speedup vs baseline: 2.3234x; 1.3949x over previous
#include <cuda_runtime.h>
#include <cuda_bf16.h>

#define NIMG  4
#define KCH   21
#define NPIX  4096      // 64*64
#define TILE  128
#define NT    32        // NPIX / TILE
#define NPAIR 528       // NT*(NT+1)/2
#define HW    16384     // 128*128
#define KPAD  64        // bf16 K row padding in global scratch
#define KS    32        // GEMM K (21 real + zero pad)
#define ROWW  40        // smem tile row width in bf16 (80B, conflict-free)

typedef unsigned long long u64;
typedef unsigned int       u32;

#define CEXP  (-0.72134752044448170f)   // -0.5 * log2(e)
#define LOG2E ( 1.44269504088896340f)

// ---- device scratch ----
__device__ __nv_bfloat16 g_sb [NIMG][NPIX][KPAD]; // seg*roi bf16, K-major rows, k in [21,32) zeroed
__device__ float         g_ppk[NIMG][NPIX][8];    // f0..f4, CEXP*|f|^2, gate, 0
__device__ float         g_partial[NIMG * NPAIR];
__device__ int           g_ctr;

// ---- packed f32x2 helpers ----
__device__ __forceinline__ u64 pk2(float lo, float hi) {
    u64 r; asm("mov.b64 %0, {%1, %2};" : "=l"(r) : "f"(lo), "f"(hi)); return r;
}
__device__ __forceinline__ void unpk2(u64 v, float& lo, float& hi) {
    asm("mov.b64 {%0, %1}, %2;" : "=f"(lo), "=f"(hi) : "l"(v));
}
#define FMA2(d, a, b, c) asm("fma.rn.f32x2 %0, %1, %2, %3;" : "=l"(d) : "l"(a), "l"(b), "l"(c))
#define MUL2(d, a, b)    asm("mul.rn.f32x2 %0, %1, %2;"     : "=l"(d) : "l"(a), "l"(b))
#define ADD2(d, a, b)    asm("add.rn.f32x2 %0, %1, %2;"     : "=l"(d) : "l"(a), "l"(b))
__device__ __forceinline__ float ex2(float x) {
    float r; asm("ex2.approx.f32 %0, %1;" : "=f"(r) : "f"(x)); return r;
}

// ---------------------------------------------------------------------------
// Kernel 1: warp-per-pixel prep (unchanged from R5; it compiled fine).
// ---------------------------------------------------------------------------
__global__ __launch_bounds__(256) void prep_kernel(const float* __restrict__ images,
                                                   const float* __restrict__ segs,
                                                   const float* __restrict__ rois,
                                                   const int*   __restrict__ labels)
{
    int gw   = (blockIdx.x * blockDim.x + threadIdx.x) >> 5;   // pixel id
    int lane = threadIdx.x & 31;
    int n = gw >> 12;
    int p = gw & (NPIX - 1);
    int y = p >> 6, x = p & 63;
    int src = (2 * y) * 128 + (2 * x);

    float roi = rois[n * HW + src];

    float v = 0.0f;
    if (lane < KCH) {
        const float* sp = segs + ((size_t)(n * KCH + lane)) * HW + src;
        float2 t0 = *(const float2*)(sp);
        float2 t1 = *(const float2*)(sp + 128);
        v = 0.25f * ((t0.x + t0.y) + (t1.x + t1.y));   // exact bilinear 2x
    }
    float mx = v;
    #pragma unroll
    for (int o = 16; o > 0; o >>= 1) mx = fmaxf(mx, __shfl_xor_sync(0xffffffffu, mx, o));

    char* row = (char*)&g_sb[n][p][0];
    if (lane < KCH)
        *(__nv_bfloat16*)(row + 2 * lane) = __float2bfloat16(v * roi);
    if (lane == 21) *(unsigned short*)(row + 42) = 0;                       // k=21
    if (lane >= 22 && lane < 27) *(u32*)(row + 44 + 4 * (lane - 22)) = 0u;  // k=22..31

    if (lane == 0) {
        int lbl = labels[n * HW + src];
        float gate = (lbl == 255) ? 1.0f : (roi - mx);
        gate = fmaxf(gate, 0.0f);
        const float* ib = images + (size_t)n * 3 * HW + src;
        float fx = (float)x * (1.0f / 50.0f);
        float fy = (float)y * (1.0f / 50.0f);
        float r  = ib[0]      * (1.0f / 15.0f);
        float g  = ib[HW]     * (1.0f / 15.0f);
        float b  = ib[2 * HW] * (1.0f / 15.0f);
        float sq = CEXP * (fx*fx + fy*fy + r*r + g*g + b*b);
        float4* pr = (float4*)&g_ppk[n][p][0];
        pr[0] = make_float4(fx, fy, r, g);
        pr[1] = make_float4(b, sq, gate, 0.0f);
    }
}

// ---------------------------------------------------------------------------
// Kernel 2: per tile-pair (128x128): C = S_P . S_Q^T via mma.sync bf16
// (m16n8k16, row.col), fused with packed-f32x2 bilateral weights.
// 16 warps = 8 m-strips x 2 n-halves; per warp 8 n-tiles x 2 k-steps.
// ---------------------------------------------------------------------------
__global__ __launch_bounds__(512, 2) void energy_kernel(float* __restrict__ out)
{
    __shared__ __align__(16) char sA[TILE * ROWW * 2];   // [128][40] bf16
    __shared__ __align__(16) char sB[TILE * ROWW * 2];
    __shared__ __align__(16) u64  qpk[64][8];            // pair-packed q features
    __shared__ float red[16];
    __shared__ int   lastflag;

    int t = blockIdx.x;
    int n = blockIdx.y;
    int tid = threadIdx.x;
    int w = tid >> 5, lane = tid & 31;

    // triangular decode (uniform)
    int ti = 0, rem = t;
    while (rem >= NT - ti) { rem -= NT - ti; ti++; }
    int tj = ti + rem;
    int p0 = ti * TILE, q0 = tj * TILE;
    bool diag = (ti == tj);

    // ---- load bf16 tiles: row r, 8-elem chunk c (only k<32 needed) ----
    {
        int r = tid >> 2, c = tid & 3;
        const uint4* srcA = (const uint4*)&g_sb[n][p0 + r][c * 8];
        const uint4* srcB = (const uint4*)&g_sb[n][q0 + r][c * 8];
        *(uint4*)(sA + r * (ROWW * 2) + c * 16) = *srcA;
        *(uint4*)(sB + r * (ROWW * 2) + c * 16) = *srcB;
    }
    // ---- pair-packed q features: qpk[q>>1][d] = (val(q_even), val(q_odd)) ----
    {
        float* qf = (float*)qpk;
        #pragma unroll
        for (int it = 0; it < 2; it++) {
            int idx = tid + it * 512;          // 1024 = 128 q * 8 d
            int q = idx >> 3, d = idx & 7;
            qf[(q >> 1) * 16 + d * 2 + (q & 1)] = g_ppk[n][q0 + q][d];
        }
    }
    __syncthreads();

    int mstrip = w >> 1;            // 0..7
    int nhalf  = w & 1;             // 0..1
    int rowA0  = mstrip * 16 + (lane >> 2);
    int rowA1  = rowA0 + 8;
    int lm4    = lane & 3;

    // ---- A fragments (both k-steps), reused across all 8 n-tiles ----
    u32 afr[2][4];
    #pragma unroll
    for (int s = 0; s < 2; s++) {
        int kw = s * 8 + lm4;       // u32 word index within row
        afr[s][0] = *(const u32*)(sA + rowA0 * (ROWW * 2) + kw * 4);
        afr[s][1] = *(const u32*)(sA + rowA1 * (ROWW * 2) + kw * 4);
        afr[s][2] = *(const u32*)(sA + rowA0 * (ROWW * 2) + (kw + 4) * 4);
        afr[s][3] = *(const u32*)(sA + rowA1 * (ROWW * 2) + (kw + 4) * 4);
    }

    // ---- p-side features, packed broadcast (rows rowA0, rowA1) ----
    u64 f0[2], f1[2], f2[2], f3[2], f4[2], sps[2], gp2[2];
    #pragma unroll
    for (int r = 0; r < 2; r++) {
        int pr = p0 + (r ? rowA1 : rowA0);
        const float4* pf = (const float4*)&g_ppk[n][pr][0];
        float4 pa = pf[0], pb = pf[1];
        f0[r] = pk2(pa.x, pa.x); f1[r] = pk2(pa.y, pa.y); f2[r] = pk2(pa.z, pa.z);
        f3[r] = pk2(pa.w, pa.w); f4[r] = pk2(pb.x, pb.x);
        sps[r] = pk2(pb.y, pb.y); gp2[r] = pk2(pb.z, pb.z);
    }
    u64 l2e = pk2(LOG2E, LOG2E);

    u64 acc2 = 0ull;

    #pragma unroll 2
    for (int tt = 0; tt < 8; tt++) {
        int jloc = nhalf * 64 + tt * 8 + (lane >> 2);    // B fragment col (q row in sB)
        // C fragment accumulators
        float d0 = 0.f, d1 = 0.f, d2_ = 0.f, d3 = 0.f;
        #pragma unroll
        for (int s = 0; s < 2; s++) {
            int kw = s * 8 + lm4;
            u32 b0 = *(const u32*)(sB + jloc * (ROWW * 2) + kw * 4);
            u32 b1 = *(const u32*)(sB + jloc * (ROWW * 2) + (kw + 4) * 4);
            asm volatile(
                "mma.sync.aligned.m16n8k16.row.col.f32.bf16.bf16.f32 "
                "{%0,%1,%2,%3}, {%4,%5,%6,%7}, {%8,%9}, {%0,%1,%2,%3};"
                : "+f"(d0), "+f"(d1), "+f"(d2_), "+f"(d3)
                : "r"(afr[s][0]), "r"(afr[s][1]), "r"(afr[s][2]), "r"(afr[s][3]),
                  "r"(b0), "r"(b1));
        }
        // q-pair features (cols j = 2*lm4 within tile, global pair index):
        int m = nhalf * 32 + tt * 4 + lm4;
        const u64* qp = &qpk[m][0];
        ulonglong2 q01 = *(const ulonglong2*)(qp);
        ulonglong2 q23 = *(const ulonglong2*)(qp + 2);
        ulonglong2 q45 = *(const ulonglong2*)(qp + 4);
        ulonglong2 q67 = *(const ulonglong2*)(qp + 6);

        #pragma unroll
        for (int r = 0; r < 2; r++) {
            u64 dot;
            MUL2(dot, f0[r], q01.x);
            FMA2(dot, f1[r], q01.y, dot);
            FMA2(dot, f2[r], q23.x, dot);
            FMA2(dot, f3[r], q23.y, dot);
            FMA2(dot, f4[r], q45.x, dot);
            u64 s2; ADD2(s2, sps[r], q45.y);      // CEXP*(|fp|^2+|fq|^2)
            u64 t2; FMA2(t2, dot, l2e, s2);       // = -0.5*log2(e)*dist2
            float tlo, thi; unpk2(t2, tlo, thi);
            float e0 = ex2(fminf(tlo, 0.0f));     // clamp folds max(d2,0)
            float e1 = ex2(fminf(thi, 0.0f));
            u64 ee = pk2(e0, e1);
            u64 cf;
            if (diag) cf = gp2[r]; else ADD2(cf, gp2[r], q67.x);
            u64 wv; MUL2(wv, ee, cf);
            u64 cc = r ? pk2(d2_, d3) : pk2(d0, d1);
            FMA2(acc2, wv, cc, acc2);
        }
    }

    float alo, ahi; unpk2(acc2, alo, ahi);
    float acc = alo + ahi;

    // ---- block reduction, deterministic per-CTA partial ----
    #pragma unroll
    for (int o = 16; o > 0; o >>= 1) acc += __shfl_down_sync(0xffffffffu, acc, o);
    if (lane == 0) red[w] = acc;
    __syncthreads();
    if (tid == 0) {
        float s = 0.0f;
        #pragma unroll
        for (int v = 0; v < 16; v++) s += red[v];
        g_partial[n * NPAIR + t] = s;
        __threadfence();
        int v = atomicAdd(&g_ctr, 1);
        lastflag = (v == NIMG * NPAIR - 1);
    }
    __syncthreads();

    // ---- last CTA: deterministic final reduction + scaling ----
    if (lastflag) {
        float s = 0.0f;
        for (int i = tid; i < NIMG * NPAIR; i += 512) s += g_partial[i];
        #pragma unroll
        for (int o = 16; o > 0; o >>= 1) s += __shfl_down_sync(0xffffffffu, s, o);
        if (lane == 0) red[w] = s;
        __syncthreads();
        if (tid == 0) {
            float tot = 0.0f;
            #pragma unroll
            for (int v = 0; v < 16; v++) tot += red[v];
            out[0] = tot * (-1e-7f / (float)NIMG);   // WEIGHT * (-sum / N)
            g_ctr = 0;                               // reset for graph replay
        }
    }
}

// ---------------------------------------------------------------------------
extern "C" void kernel_launch(void* const* d_in, const int* in_sizes, int n_in,
                              void* d_out, int out_size)
{
    const float* images = (const float*)d_in[0];
    const float* segs   = (const float*)d_in[1];
    const float* rois   = (const float*)d_in[2];
    const int*   labels = (const int*)  d_in[3];

    prep_kernel<<<(NIMG * NPIX * 32) / 256, 256>>>(images, segs, rois, labels);
    dim3 grid(NPAIR, NIMG);
    energy_kernel<<<grid, 512>>>((float*)d_out);
}

// round 8
// speedup vs baseline: 2.8816x; 1.2403x over previous
#include <cuda_runtime.h>
#include <cuda_bf16.h>

#define NIMG  4
#define KCH   21
#define NPIX  4096      // 64*64
#define TILE  128
#define NT    32        // NPIX / TILE
#define NPAIR 528       // NT*(NT+1)/2
#define HW    16384     // 128*128
#define KPAD  64        // bf16 K row padding in global scratch
#define ROWW  40        // smem tile row width in bf16 (80B, conflict-free)
#define QROW  10        // qpk row stride in u64 (80B, 16B-aligned, conflict-free)

typedef unsigned long long u64;
typedef unsigned int       u32;

#define CEXP  (-0.72134752044448170f)   // -0.5 * log2(e)
#define LOG2E ( 1.44269504088896340f)

// ---- device scratch ----
__device__ __nv_bfloat16 g_sb [NIMG][NPIX][KPAD]; // seg*roi bf16, K-major rows, k in [21,32) zeroed
__device__ float         g_ppk[NIMG][NPIX][8];    // f0..f4, CEXP*|f|^2, gate, 0
__device__ float         g_partial[NIMG * NPAIR];
__device__ int           g_ctr;

// ---- packed f32x2 helpers ----
__device__ __forceinline__ u64 pk2(float lo, float hi) {
    u64 r; asm("mov.b64 %0, {%1, %2};" : "=l"(r) : "f"(lo), "f"(hi)); return r;
}
__device__ __forceinline__ void unpk2(u64 v, float& lo, float& hi) {
    asm("mov.b64 {%0, %1}, %2;" : "=f"(lo), "=f"(hi) : "l"(v));
}
#define FMA2(d, a, b, c) asm("fma.rn.f32x2 %0, %1, %2, %3;" : "=l"(d) : "l"(a), "l"(b), "l"(c))
#define MUL2(d, a, b)    asm("mul.rn.f32x2 %0, %1, %2;"     : "=l"(d) : "l"(a), "l"(b))
#define ADD2(d, a, b)    asm("add.rn.f32x2 %0, %1, %2;"     : "=l"(d) : "l"(a), "l"(b))
__device__ __forceinline__ float ex2(float x) {
    float r; asm("ex2.approx.f32 %0, %1;" : "=f"(r) : "f"(x)); return r;
}
__device__ __forceinline__ u32 smem_u32(const void* p) {
    u32 a; asm("{ .reg .u64 t; cvta.to.shared.u64 t, %1; cvt.u32.u64 %0, t; }" : "=r"(a) : "l"(p));
    return a;
}
#define LDMX4(r, addr) \
    asm volatile("ldmatrix.sync.aligned.m8n8.x4.shared.b16 {%0,%1,%2,%3}, [%4];" \
        : "=r"((r)[0]), "=r"((r)[1]), "=r"((r)[2]), "=r"((r)[3]) : "r"(addr))

// ---------------------------------------------------------------------------
// Kernel 1: warp-per-2-pixels prep. lane k<21: float4 covers both pixels'
// 2x2 source quads; two shfl-max reductions; lanes 0/1 write feature rows.
// ---------------------------------------------------------------------------
__global__ __launch_bounds__(256) void prep_kernel(const float* __restrict__ images,
                                                   const float* __restrict__ segs,
                                                   const float* __restrict__ rois,
                                                   const int*   __restrict__ labels)
{
    int gw   = (blockIdx.x * blockDim.x + threadIdx.x) >> 5;   // pixel-pair id
    int lane = threadIdx.x & 31;
    int n  = gw >> 11;              // 2048 pairs per image
    int pr = gw & 2047;
    int y  = pr >> 5;               // 0..63
    int xh = pr & 31;               // x = 2*xh, 2*xh+1
    int p_e = y * 64 + 2 * xh;
    int src = (2 * y) * 128 + 4 * xh;

    float4 roi4 = make_float4(0.f, 0.f, 0.f, 0.f);
    if (lane == 0) roi4 = *(const float4*)(rois + n * HW + src);
    float roi_e = __shfl_sync(0xffffffffu, roi4.x, 0);
    float roi_o = __shfl_sync(0xffffffffu, roi4.z, 0);

    float v_e = 0.0f, v_o = 0.0f;
    if (lane < KCH) {
        const float* sp = segs + ((size_t)(n * KCH + lane)) * HW + src;
        float4 a0 = *(const float4*)(sp);
        float4 a1 = *(const float4*)(sp + 128);
        v_e = 0.25f * ((a0.x + a0.y) + (a1.x + a1.y));   // exact bilinear 2x
        v_o = 0.25f * ((a0.z + a0.w) + (a1.z + a1.w));
    }
    float me = v_e, mo = v_o;
    #pragma unroll
    for (int o = 16; o > 0; o >>= 1) {
        me = fmaxf(me, __shfl_xor_sync(0xffffffffu, me, o));
        mo = fmaxf(mo, __shfl_xor_sync(0xffffffffu, mo, o));
    }

    char* row_e = (char*)&g_sb[n][p_e][0];
    char* row_o = row_e + KPAD * 2;
    if (lane < KCH) {
        *(__nv_bfloat16*)(row_e + 2 * lane) = __float2bfloat16(v_e * roi_e);
        *(__nv_bfloat16*)(row_o + 2 * lane) = __float2bfloat16(v_o * roi_o);
    }
    if (lane == 21) {
        *(unsigned short*)(row_e + 42) = 0;
        *(unsigned short*)(row_o + 42) = 0;
    }
    if (lane >= 22 && lane < 27) {
        *(u32*)(row_e + 44 + 4 * (lane - 22)) = 0u;
        *(u32*)(row_o + 44 + 4 * (lane - 22)) = 0u;
    }

    if (lane < 2) {
        float roi = lane ? roi_o : roi_e;
        float mx  = lane ? mo    : me;
        int s     = src + 2 * lane;
        int lbl = labels[n * HW + s];
        float gate = (lbl == 255) ? 1.0f : (roi - mx);
        gate = fmaxf(gate, 0.0f);
        const float* ib = images + (size_t)n * 3 * HW + s;
        float fx = (float)(2 * xh + lane) * (1.0f / 50.0f);
        float fy = (float)y * (1.0f / 50.0f);
        float r  = ib[0]      * (1.0f / 15.0f);
        float g  = ib[HW]     * (1.0f / 15.0f);
        float b  = ib[2 * HW] * (1.0f / 15.0f);
        float sq = CEXP * (fx*fx + fy*fy + r*r + g*g + b*b);
        float4* pw = (float4*)&g_ppk[n][p_e + lane][0];
        pw[0] = make_float4(fx, fy, r, g);
        pw[1] = make_float4(b, sq, gate, 0.0f);
    }
}

// ---------------------------------------------------------------------------
// Kernel 2: per tile-pair (128x128): C = S_P . S_Q^T via mma.sync bf16
// (m16n8k16, row.col) with ldmatrix fragment loads, fused packed-f32x2
// bilateral weights. 16 warps = 8 m-strips x 2 n-halves.
// ---------------------------------------------------------------------------
__global__ __launch_bounds__(512, 2) void energy_kernel(float* __restrict__ out)
{
    __shared__ __align__(16) char sA[TILE * ROWW * 2];   // [128][40] bf16
    __shared__ __align__(16) char sB[TILE * ROWW * 2];
    __shared__ __align__(16) u64  qpk[64][QROW];         // pair-packed q features (80B rows)
    __shared__ float red[16];
    __shared__ int   lastflag;

    int t = blockIdx.x;
    int n = blockIdx.y;
    int tid = threadIdx.x;
    int w = tid >> 5, lane = tid & 31;

    // triangular decode (uniform)
    int ti = 0, rem = t;
    while (rem >= NT - ti) { rem -= NT - ti; ti++; }
    int tj = ti + rem;
    int p0 = ti * TILE, q0 = tj * TILE;
    bool diag = (ti == tj);

    // ---- load bf16 tiles (k<32 only) ----
    {
        int r = tid >> 2, c = tid & 3;
        *(uint4*)(sA + r * (ROWW * 2) + c * 16) = *(const uint4*)&g_sb[n][p0 + r][c * 8];
        *(uint4*)(sB + r * (ROWW * 2) + c * 16) = *(const uint4*)&g_sb[n][q0 + r][c * 8];
    }
    // ---- pair-packed q features; diag zeroes the q-gate (d==6) ----
    {
        float* qf = (float*)qpk;
        #pragma unroll
        for (int it = 0; it < 2; it++) {
            int idx = tid + it * 512;          // 1024 = 128 q * 8 d
            int q = idx >> 3, d = idx & 7;
            float v = g_ppk[n][q0 + q][d];
            if (d == 6 && diag) v = 0.0f;
            qf[(q >> 1) * (QROW * 2) + d * 2 + (q & 1)] = v;
        }
    }
    __syncthreads();

    int mstrip = w >> 1;            // 0..7
    int nhalf  = w & 1;             // 0..1
    int lm4    = lane & 3;
    u32 sAu = smem_u32(sA), sBu = smem_u32(sB);

    // ---- A fragments via 2x ldmatrix.x4 ----
    u32 afr[2][4];
    {
        int arow = mstrip * 16 + (lane & 7) + ((lane >> 3) & 1) * 8;
        u32 aaddr = sAu + arow * (ROWW * 2) + (lane >> 4) * 16;
        LDMX4(afr[0], aaddr);
        LDMX4(afr[1], aaddr + 32);
    }
    u32 baddr = sBu + (nhalf * 64 + (lane & 7)) * (ROWW * 2) + (lane >> 3) * 16;

    // ---- p-side features, packed broadcast (rows rowA0, rowA0+8) ----
    int rowA0 = mstrip * 16 + (lane >> 2);
    u64 f0[2], f1[2], f2[2], f3[2], f4[2], sps[2], gp2[2];
    #pragma unroll
    for (int r = 0; r < 2; r++) {
        const float4* pf = (const float4*)&g_ppk[n][p0 + rowA0 + r * 8][0];
        float4 pa = pf[0], pb = pf[1];
        f0[r] = pk2(pa.x, pa.x); f1[r] = pk2(pa.y, pa.y); f2[r] = pk2(pa.z, pa.z);
        f3[r] = pk2(pa.w, pa.w); f4[r] = pk2(pb.x, pb.x);
        sps[r] = pk2(pb.y, pb.y); gp2[r] = pk2(pb.z, pb.z);
    }
    u64 l2e = pk2(LOG2E, LOG2E);
    const char* qb = (const char*)qpk + (nhalf * 32 + lm4) * (QROW * 8);

    u64 acc2 = 0ull;

    #pragma unroll
    for (int tt = 0; tt < 8; tt++) {
        // B fragments: one ldmatrix.x4 = {b0s0, b1s0, b0s1, b1s1}
        u32 bfr[4];
        LDMX4(bfr, baddr + tt * (8 * ROWW * 2));

        float d0 = 0.f, d1 = 0.f, d2_ = 0.f, d3 = 0.f;
        asm volatile(
            "mma.sync.aligned.m16n8k16.row.col.f32.bf16.bf16.f32 "
            "{%0,%1,%2,%3}, {%4,%5,%6,%7}, {%8,%9}, {%0,%1,%2,%3};"
            : "+f"(d0), "+f"(d1), "+f"(d2_), "+f"(d3)
            : "r"(afr[0][0]), "r"(afr[0][1]), "r"(afr[0][2]), "r"(afr[0][3]),
              "r"(bfr[0]), "r"(bfr[1]));
        asm volatile(
            "mma.sync.aligned.m16n8k16.row.col.f32.bf16.bf16.f32 "
            "{%0,%1,%2,%3}, {%4,%5,%6,%7}, {%8,%9}, {%0,%1,%2,%3};"
            : "+f"(d0), "+f"(d1), "+f"(d2_), "+f"(d3)
            : "r"(afr[1][0]), "r"(afr[1][1]), "r"(afr[1][2]), "r"(afr[1][3]),
              "r"(bfr[2]), "r"(bfr[3]));

        // q-pair features: immediate offsets off qb (full unroll)
        const char* qp = qb + tt * (4 * QROW * 8);
        ulonglong2 q01 = *(const ulonglong2*)(qp);
        ulonglong2 q23 = *(const ulonglong2*)(qp + 16);
        ulonglong2 q45 = *(const ulonglong2*)(qp + 32);
        ulonglong2 q67 = *(const ulonglong2*)(qp + 48);

        #pragma unroll
        for (int r = 0; r < 2; r++) {
            u64 dot;
            MUL2(dot, f0[r], q01.x);
            FMA2(dot, f1[r], q01.y, dot);
            FMA2(dot, f2[r], q23.x, dot);
            FMA2(dot, f3[r], q23.y, dot);
            FMA2(dot, f4[r], q45.x, dot);
            u64 s2; ADD2(s2, sps[r], q45.y);      // CEXP*(|fp|^2+|fq|^2)
            u64 t2; FMA2(t2, dot, l2e, s2);       // = -0.5*log2(e)*dist2
            float tlo, thi; unpk2(t2, tlo, thi);
            float e0 = ex2(fminf(tlo, 0.0f));     // clamp folds max(d2,0)
            float e1 = ex2(fminf(thi, 0.0f));
            u64 ee = pk2(e0, e1);
            u64 cf; ADD2(cf, gp2[r], q67.x);      // q-gate pre-zeroed on diag
            u64 wv; MUL2(wv, ee, cf);
            u64 cc = r ? pk2(d2_, d3) : pk2(d0, d1);
            FMA2(acc2, wv, cc, acc2);
        }
    }

    float alo, ahi; unpk2(acc2, alo, ahi);
    float acc = alo + ahi;

    // ---- block reduction, deterministic per-CTA partial ----
    #pragma unroll
    for (int o = 16; o > 0; o >>= 1) acc += __shfl_down_sync(0xffffffffu, acc, o);
    if (lane == 0) red[w] = acc;
    __syncthreads();
    if (tid == 0) {
        float s = 0.0f;
        #pragma unroll
        for (int v = 0; v < 16; v++) s += red[v];
        g_partial[n * NPAIR + t] = s;
        __threadfence();
        int v = atomicAdd(&g_ctr, 1);
        lastflag = (v == NIMG * NPAIR - 1);
    }
    __syncthreads();

    // ---- last CTA: deterministic final reduction + scaling ----
    if (lastflag) {
        float s = 0.0f;
        for (int i = tid; i < NIMG * NPAIR; i += 512) s += g_partial[i];
        #pragma unroll
        for (int o = 16; o > 0; o >>= 1) s += __shfl_down_sync(0xffffffffu, s, o);
        if (lane == 0) red[w] = s;
        __syncthreads();
        if (tid == 0) {
            float tot = 0.0f;
            #pragma unroll
            for (int v = 0; v < 16; v++) tot += red[v];
            out[0] = tot * (-1e-7f / (float)NIMG);   // WEIGHT * (-sum / N)
            g_ctr = 0;                               // reset for graph replay
        }
    }
}

// ---------------------------------------------------------------------------
extern "C" void kernel_launch(void* const* d_in, const int* in_sizes, int n_in,
                              void* d_out, int out_size)
{
    const float* images = (const float*)d_in[0];
    const float* segs   = (const float*)d_in[1];
    const float* rois   = (const float*)d_in[2];
    const int*   labels = (const int*)  d_in[3];

    prep_kernel<<<(NIMG * NPIX / 2) * 32 / 256, 256>>>(images, segs, rois, labels);
    dim3 grid(NPAIR, NIMG);
    energy_kernel<<<grid, 512>>>((float*)d_out);
}